// round 9
// baseline (speedup 1.0000x reference)
#include <cuda_runtime.h>
#include <math.h>
#include <float.h>
#include <stdint.h>

// ---------------- problem constants ----------------
#define NB   2
#define NN   1024
#define NKE  32
#define DIM  512
#define MSG  256
#define NH   16
#define HD   64
#define ROWS_MSG  (NB*NN*NKE)   // 65536
#define ROWS_NODE (NB*NN)       // 2048

// ---------------- scratch (static device globals; no runtime alloc) ----------------
__device__ float g_bufA[ROWS_MSG*MSG];
__device__ float g_bufB[ROWS_MSG*MSG];
__device__ float g_h1  [ROWS_MSG*4*MSG];
__device__ float g_node_msg[ROWS_NODE*MSG];
__device__ float g_node_tgt[ROWS_NODE*MSG];
__device__ float g_ab  [ROWS_MSG*NH];
__device__ float g_attn[ROWS_MSG*NH];
__device__ float g_P   [ROWS_NODE*NH*MSG];
__device__ float g_og  [ROWS_NODE*NH*HD];
__device__ float g_gate[ROWS_NODE*MSG];
__device__ float g_gatg[ROWS_NODE*NH*HD];
__device__ float g_o   [ROWS_NODE*MSG];
__device__ float g_dh  [ROWS_NODE*DIM];
__device__ float g_node2[ROWS_NODE*DIM];
__device__ float g_nln [ROWS_NODE*DIM];
__device__ float g_h2  [ROWS_NODE*4*DIM];

// ---------------- tf32 tensor-core GEMM, cp.async 3-stage pipeline ----------------
// Block tile 128x128, BK=16, 256 threads = 8 warps in 2(m) x 4(n), warp tile 64x32.
// A smem: [BM][AS_STR] (k contiguous); B smem: [BK][BS_STR] (n contiguous).
// 3 stages, one __syncthreads per iteration (always-commit group accounting).
#define BM 128
#define BN 128
#define BK 16
#define AS_STR 20    // frag bank (20g+t4)%32 all-distinct
#define BS_STR 136   // frag bank (8t4+g)%32 all-distinct
#define A_TILE_F (BM*AS_STR)   // 2560 floats
#define B_TILE_F (BK*BS_STR)   // 2176 floats
#define NSTAGE 3

__device__ __forceinline__ float gelu_exact(float x) {
    return 0.5f * x * (1.0f + erff(x * 0.70710678118654752f));
}
__device__ __forceinline__ float sigmoidf_(float x) {
    return 1.0f / (1.0f + expf(-x));
}
__device__ __forceinline__ void mma8(float* c, const uint32_t* a, const uint32_t* b) {
    asm("mma.sync.aligned.m16n8k8.row.col.f32.tf32.tf32.f32 "
        "{%0,%1,%2,%3},{%4,%5,%6,%7},{%8,%9},{%0,%1,%2,%3};"
        : "+f"(c[0]), "+f"(c[1]), "+f"(c[2]), "+f"(c[3])
        : "r"(a[0]), "r"(a[1]), "r"(a[2]), "r"(a[3]), "r"(b[0]), "r"(b[1]));
}
__device__ __forceinline__ void cp16(uint32_t dst, const void* src, int bytes) {
    asm volatile("cp.async.ca.shared.global [%0], [%1], 16, %2;\n"
                 :: "r"(dst), "l"(src), "r"(bytes));
}

// MODE: 0 plain | 1 +bias | 2 gelu(+bias) | 3 leaky | 4 (+bias)*rowmask
//       5 msg0 (acc + gather(node_msg)*mask_bw + node_tgt)
//       6 aux1 + aux2 + acc | 7 aux1 + acc + bias | 8 sigmoid(aux1)*acc
// Requires: M % 128 == 0, K % 16 == 0 (true for every call site).
template<int MODE>
__global__ __launch_bounds__(256) void gemm_tc(
    const float* __restrict__ A, int lda,
    const float* __restrict__ B, int ldb,
    float* __restrict__ C, int ldc,
    int M, int N, int K,
    const float* __restrict__ bias,
    const float* __restrict__ aux1,
    const float* __restrict__ aux2,
    const int*   __restrict__ idx,
    const float* __restrict__ auxf,
    const int*   __restrict__ rowmask,
    int sA, int sB, int sC, int sAux)
{
    A += (size_t)blockIdx.z * sA;
    B += (size_t)blockIdx.z * sB;
    C += (size_t)blockIdx.z * sC;
    const float* aux1z = aux1 ? aux1 + (size_t)blockIdx.z * sAux : aux1;

    __shared__ __align__(16) float sm[NSTAGE*A_TILE_F + NSTAGE*B_TILE_F];
    uint32_t smem_u32 = (uint32_t)__cvta_generic_to_shared(sm);

    const int tid  = threadIdx.x;
    const int lane = tid & 31;
    const int warp = tid >> 5;
    const int warpM = warp >> 2;          // 0..1  (64 rows each)
    const int warpN = warp & 3;           // 0..3  (32 cols each)
    const int g  = lane >> 2;             // 0..7
    const int t4 = lane & 3;              // 0..3
    const int row0 = blockIdx.y * BM, col0 = blockIdx.x * BN;

    float ac[4][4][4];
    #pragma unroll
    for (int mi = 0; mi < 4; mi++)
        #pragma unroll
        for (int ni = 0; ni < 4; ni++)
            #pragma unroll
            for (int cr = 0; cr < 4; cr++) ac[mi][ni][cr] = 0.f;

    const int T = K / BK;

    // ---- stage loader: ALWAYS commits a group (empty when kt >= K) ----
    auto load_stage = [&](int kt, int s) {
        if (kt < K) {
            // A tile: 128 rows x 16 k = 512 16B-chunks; 2 per thread
            #pragma unroll
            for (int i = 0; i < 2; i++) {
                int c = i * 256 + tid;
                int row = c >> 2, k4 = (c & 3) << 2;
                const float* src = A + (size_t)(row0 + row) * lda + kt + k4;
                uint32_t dst = smem_u32 + ((s * A_TILE_F + row * AS_STR + k4) << 2);
                cp16(dst, src, 16);
            }
            // B tile: 16 k-rows x 128 n = 512 chunks; 2 per thread
            #pragma unroll
            for (int i = 0; i < 2; i++) {
                int c = i * 256 + tid;
                int kk = c >> 5, n4 = (c & 31) << 2;
                int gc = col0 + n4;
                int rem = N - gc;
                int bytes = rem >= 4 ? 16 : (rem > 0 ? rem * 4 : 0);
                const float* src = B + (size_t)(kt + kk) * ldb + (rem > 0 ? gc : 0);
                uint32_t dst = smem_u32 + ((NSTAGE * A_TILE_F + s * B_TILE_F + kk * BS_STR + n4) << 2);
                cp16(dst, src, bytes);
            }
        }
        asm volatile("cp.async.commit_group;\n");
    };

    // prologue: stages 0,1 (group per stage, empty-safe)
    load_stage(0, 0);
    load_stage(BK, 1);

    for (int t = 0; t < T; t++) {
        // all but the newest committed group done => load(t) complete
        asm volatile("cp.async.wait_group 1;\n");
        __syncthreads();   // also fences compute(t-1): safe to overwrite slot (t+2)%3

        load_stage((t + 2) * BK, (t + 2) % NSTAGE);

        const float* As_ = &sm[(t % NSTAGE) * A_TILE_F];
        const float* Bs_ = &sm[NSTAGE * A_TILE_F + (t % NSTAGE) * B_TILE_F];

        #pragma unroll
        for (int k8 = 0; k8 < BK; k8 += 8) {
            uint32_t af[4][4], bf[4][2];
            #pragma unroll
            for (int mi = 0; mi < 4; mi++) {
                int m0 = warpM * 64 + mi * 16 + g;
                af[mi][0] = __float_as_uint(As_[(m0    ) * AS_STR + k8 + t4    ]);
                af[mi][1] = __float_as_uint(As_[(m0 + 8) * AS_STR + k8 + t4    ]);
                af[mi][2] = __float_as_uint(As_[(m0    ) * AS_STR + k8 + t4 + 4]);
                af[mi][3] = __float_as_uint(As_[(m0 + 8) * AS_STR + k8 + t4 + 4]);
            }
            #pragma unroll
            for (int ni = 0; ni < 4; ni++) {
                int n0 = warpN * 32 + ni * 8 + g;
                bf[ni][0] = __float_as_uint(Bs_[(k8 + t4    ) * BS_STR + n0]);
                bf[ni][1] = __float_as_uint(Bs_[(k8 + t4 + 4) * BS_STR + n0]);
            }
            #pragma unroll
            for (int mi = 0; mi < 4; mi++)
                #pragma unroll
                for (int ni = 0; ni < 4; ni++)
                    mma8(ac[mi][ni], af[mi], bf[ni]);
        }
    }

    // epilogue
    #pragma unroll
    for (int mi = 0; mi < 4; mi++) {
        #pragma unroll
        for (int cr = 0; cr < 4; cr++) {
            int r = row0 + warpM * 64 + mi * 16 + g + ((cr >> 1) ? 8 : 0);
            #pragma unroll
            for (int ni = 0; ni < 4; ni++) {
                int c = col0 + warpN * 32 + ni * 8 + t4 * 2 + (cr & 1);
                if (c >= N) continue;
                float v = ac[mi][ni][cr];
                if (MODE == 1) {
                    v += bias[c];
                } else if (MODE == 2) {
                    v = gelu_exact(v + bias[c]);
                } else if (MODE == 3) {
                    v = (v > 0.f) ? v : 0.01f * v;
                } else if (MODE == 4) {
                    v += bias[c];
                    if (rowmask[r] == 0) v = 0.f;
                } else if (MODE == 5) {
                    int bidx = r >> 15;            // 32768 msg rows per batch
                    int node = r >> 5;             // b*NN + n
                    v += aux1z[(size_t)(bidx*NN + idx[r]) * MSG + c] * auxf[r]
                       + aux2[(size_t)node * MSG + c];
                } else if (MODE == 6) {
                    v = aux1z[(size_t)r*ldc + c] + aux2[(size_t)r*ldc + c] + v;
                } else if (MODE == 7) {
                    v = aux1z[(size_t)r*ldc + c] + v + bias[c];
                } else if (MODE == 8) {
                    v *= sigmoidf_(aux1z[(size_t)r*ldc + c]);
                }
                C[(size_t)r * ldc + c] = v;
            }
        }
    }
}

// ---------------- LayerNorm: one warp per row, float4 ----------------
__global__ __launch_bounds__(256) void ln_warp_kernel(
    const float* __restrict__ x, float* __restrict__ y,
    const float* __restrict__ g, const float* __restrict__ b, int width)
{
    int wid  = threadIdx.x >> 5;
    int lane = threadIdx.x & 31;
    int row  = blockIdx.x * 8 + wid;
    const float4* xr = reinterpret_cast<const float4*>(x + (size_t)row * width);
    int w4 = width >> 2;

    float s = 0.f, sq = 0.f;
    for (int i = lane; i < w4; i += 32) {
        float4 v = xr[i];
        s  += v.x + v.y + v.z + v.w;
        sq += v.x*v.x + v.y*v.y + v.z*v.z + v.w*v.w;
    }
    #pragma unroll
    for (int o = 16; o > 0; o >>= 1) {
        s  += __shfl_xor_sync(0xFFFFFFFFu, s,  o);
        sq += __shfl_xor_sync(0xFFFFFFFFu, sq, o);
    }
    float mean = s / width;
    float var  = sq / width - mean * mean;
    float rstd = rsqrtf(var + 1e-5f);

    const float4* g4 = reinterpret_cast<const float4*>(g);
    const float4* b4 = reinterpret_cast<const float4*>(b);
    float4* yr = reinterpret_cast<float4*>(y + (size_t)row * width);
    for (int i = lane; i < w4; i += 32) {
        float4 v = xr[i], gg = g4[i], bb = b4[i];
        float4 o;
        o.x = (v.x - mean) * rstd * gg.x + bb.x;
        o.y = (v.y - mean) * rstd * gg.y + bb.y;
        o.z = (v.z - mean) * rstd * gg.z + bb.z;
        o.w = (v.w - mean) * rstd * gg.w + bb.w;
        yr[i] = o;
    }
}

// ---------------- masked softmax over k, per (node, head) ----------------
__global__ __launch_bounds__(512) void softmax_kernel(
    const float* __restrict__ ab, const int* __restrict__ em,
    float* __restrict__ attn)
{
    int node = blockIdx.x;
    int h = threadIdx.x >> 5, k = threadIdx.x & 31;
    int ridx = node * NKE + k;
    float v = em[ridx] ? ab[(size_t)ridx * NH + h] : -FLT_MAX;
    float m = v;
    #pragma unroll
    for (int o = 16; o > 0; o >>= 1) m = fmaxf(m, __shfl_xor_sync(0xFFFFFFFFu, m, o));
    float e = expf(v - m);
    float s = e;
    #pragma unroll
    for (int o = 16; o > 0; o >>= 1) s += __shfl_xor_sync(0xFFFFFFFFu, s, o);
    attn[(size_t)ridx * NH + h] = e / s;
}

// ---------------- P[node,h,c] = sum_k attn[k,h] * msg[k,c] ----------------
__global__ __launch_bounds__(256) void pmat_kernel(
    const float* __restrict__ msg, const float* __restrict__ attn,
    float* __restrict__ P)
{
    __shared__ float ms[NKE][MSG];   // 32 KB
    __shared__ float as[NKE][NH];    // 2 KB
    int node = blockIdx.x;
    for (int e = threadIdx.x; e < NKE * MSG; e += 256)
        ms[e >> 8][e & 255] = msg[(size_t)node * NKE * MSG + e];
    for (int e = threadIdx.x; e < NKE * NH; e += 256)
        as[e >> 4][e & 15] = attn[(size_t)node * NKE * NH + e];
    __syncthreads();
    int c = threadIdx.x;   // 0..255
    #pragma unroll 1
    for (int h = 0; h < NH; h++) {
        float acc = 0.f;
        #pragma unroll
        for (int k = 0; k < NKE; k++) acc = fmaf(as[k][h], ms[k][c], acc);
        P[(size_t)node * NH * MSG + h * MSG + c] = acc;
    }
}

// ---------------- gated mean-pool over k ----------------
__global__ __launch_bounds__(256) void pool_kernel(
    const float* __restrict__ msg, const int* __restrict__ em,
    const float* __restrict__ gate_lin, float* __restrict__ o)
{
    int node = blockIdx.x;
    __shared__ float emf[NKE];
    __shared__ float cnt_s;
    if (threadIdx.x < NKE) emf[threadIdx.x] = (float)em[node * NKE + threadIdx.x];
    __syncthreads();
    if (threadIdx.x == 0) {
        float c = 0.f;
        for (int k = 0; k < NKE; k++) c += emf[k];
        cnt_s = c;
    }
    __syncthreads();
    float inv = 1.f / (cnt_s + 1e-6f);
    int c = threadIdx.x;   // 0..255
    float acc = 0.f;
    #pragma unroll
    for (int k = 0; k < NKE; k++)
        acc = fmaf(emf[k], msg[((size_t)node * NKE + k) * MSG + c], acc);
    float gl = gate_lin[(size_t)node * MSG + c];
    o[(size_t)node * MSG + c] = acc * inv * sigmoidf_(gl);
}

// ---------------- host side ----------------
struct EP {
    const float* bias = nullptr;
    const float* a1 = nullptr;
    const float* a2 = nullptr;
    const int*   idx = nullptr;
    const float* af = nullptr;
    const int*   rm = nullptr;
    int sA = 0, sB = 0, sC = 0, sAux = 0, Z = 1;
};

template<int MODE>
static void gemm(const float* A, int lda, const float* B, int ldb,
                 float* C, int ldc, int M, int N, int K, EP e = EP())
{
    dim3 g((N + BN - 1) / BN, (M + BM - 1) / BM, e.Z);
    gemm_tc<MODE><<<g, 256>>>(A, lda, B, ldb, C, ldc, M, N, K,
                              e.bias, e.a1, e.a2, e.idx, e.af, e.rm,
                              e.sA, e.sB, e.sC, e.sAux);
}

extern "C" void kernel_launch(void* const* d_in, const int* in_sizes, int n_in,
                              void* d_out, int out_size)
{
    const float* node_repr  = (const float*)d_in[0];
    const float* edge_repr  = (const float*)d_in[1];
    const int*   edge_index = (const int*)  d_in[2];
    const int*   edge_mask  = (const int*)  d_in[3];
    const float* mask_bw    = (const float*)d_in[4];
    const float* W_edge_msg = (const float*)d_in[5];
    const float* W_node_src = (const float*)d_in[6];
    const float* W_node_tgt = (const float*)d_in[7];
    const float* msg_ln_g   = (const float*)d_in[8];
    const float* msg_ln_b   = (const float*)d_in[9];
    const float* msg_W1     = (const float*)d_in[10];
    const float* msg_b1     = (const float*)d_in[11];
    const float* msg_W2     = (const float*)d_in[12];
    const float* msg_b2     = (const float*)d_in[13];
    const float* W_gate     = (const float*)d_in[14];
    const float* b_gate     = (const float*)d_in[15];
    const float* W_out      = (const float*)d_in[16];
    const float* W_msg      = (const float*)d_in[17];
    const float* W_attn_bias= (const float*)d_in[18];
    const float* W_gat_value= (const float*)d_in[19];
    const float* W_gat_gate = (const float*)d_in[20];
    const float* b_gat_gate = (const float*)d_in[21];
    const float* W_gat_out  = (const float*)d_in[22];
    const float* node_ln_g  = (const float*)d_in[23];
    const float* node_ln_b  = (const float*)d_in[24];
    const float* node_W1    = (const float*)d_in[25];
    const float* node_b1    = (const float*)d_in[26];
    const float* node_W2    = (const float*)d_in[27];
    const float* node_b2    = (const float*)d_in[28];

    float *p_bufA, *p_bufB, *p_h1, *p_node_msg, *p_node_tgt,
          *p_ab, *p_attn, *p_P, *p_og, *p_gate, *p_gatg, *p_o, *p_dh,
          *p_node2, *p_nln, *p_h2;
    cudaGetSymbolAddress((void**)&p_bufA, g_bufA);
    cudaGetSymbolAddress((void**)&p_bufB, g_bufB);
    cudaGetSymbolAddress((void**)&p_h1,  g_h1);
    cudaGetSymbolAddress((void**)&p_node_msg, g_node_msg);
    cudaGetSymbolAddress((void**)&p_node_tgt, g_node_tgt);
    cudaGetSymbolAddress((void**)&p_ab,  g_ab);
    cudaGetSymbolAddress((void**)&p_attn,g_attn);
    cudaGetSymbolAddress((void**)&p_P,   g_P);
    cudaGetSymbolAddress((void**)&p_og,  g_og);
    cudaGetSymbolAddress((void**)&p_gate,g_gate);
    cudaGetSymbolAddress((void**)&p_gatg,g_gatg);
    cudaGetSymbolAddress((void**)&p_o,   g_o);
    cudaGetSymbolAddress((void**)&p_dh,  g_dh);
    cudaGetSymbolAddress((void**)&p_node2,g_node2);
    cudaGetSymbolAddress((void**)&p_nln, g_nln);
    cudaGetSymbolAddress((void**)&p_h2,  g_h2);

    float* out = (float*)d_out;

    // buffer aliases (lifetimes disjoint)
    float* p_msg0 = p_bufA;   // until ln reads it
    float* p_msg  = p_bufA;   // final messages (overwrites msg0 after it is dead)
    float* p_ln   = p_bufB;   // until h1 GEMM reads it
    float* p_t    = p_bufB;   // leaky(msg@W_msg) (overwrites ln after it is dead)

    // 1) node projections
    gemm<0>(node_repr, DIM, W_node_src, MSG, p_node_msg, MSG, ROWS_NODE, MSG, DIM);
    gemm<0>(node_repr, DIM, W_node_tgt, MSG, p_node_tgt, MSG, ROWS_NODE, MSG, DIM);

    // 2) msg0 = edge_repr@W_edge_msg + gather(node_msg)*mask_bw + node_tgt
    { EP e; e.a1 = p_node_msg; e.a2 = p_node_tgt; e.idx = edge_index; e.af = mask_bw;
      gemm<5>(edge_repr, MSG, W_edge_msg, MSG, p_msg0, MSG, ROWS_MSG, MSG, MSG, e); }

    // 3) msg MLP: LN -> gelu(W1) -> W2 (+mask-zero)
    ln_warp_kernel<<<ROWS_MSG/8, 256>>>(p_msg0, p_ln, msg_ln_g, msg_ln_b, MSG);
    { EP e; e.bias = msg_b1;
      gemm<2>(p_ln, MSG, msg_W1, 4*MSG, p_h1, 4*MSG, ROWS_MSG, 4*MSG, MSG, e); }
    { EP e; e.bias = msg_b2; e.rm = edge_mask;
      gemm<4>(p_h1, 4*MSG, msg_W2, MSG, p_msg, MSG, ROWS_MSG, MSG, 4*MSG, e); }

    // 4) pooled gated path: gate_lin, pool, dh = o@W_out
    { EP e; e.bias = b_gate;
      gemm<1>(node_repr, DIM, W_gate, MSG, p_gate, MSG, ROWS_NODE, MSG, DIM, e); }
    pool_kernel<<<ROWS_NODE, 256>>>(p_msg, edge_mask, p_gate, p_o);
    gemm<0>(p_o, MSG, W_out, DIM, p_dh, DIM, ROWS_NODE, DIM, MSG);

    // 5) GAT path
    gemm<3>(p_msg, MSG, W_msg, MSG, p_t, MSG, ROWS_MSG, MSG, MSG);            // leaky(msg@W_msg)
    gemm<0>(p_t, MSG, W_attn_bias, NH, p_ab, NH, ROWS_MSG, NH, MSG);          // ab
    softmax_kernel<<<ROWS_NODE, 512>>>(p_ab, edge_mask, p_attn);
    pmat_kernel<<<ROWS_NODE, 256>>>(p_msg, p_attn, p_P);                      // P = attn^T msg
    { EP e; e.bias = b_gat_gate;
      gemm<1>(node_repr, DIM, W_gat_gate, NH*HD, p_gatg, NH*HD, ROWS_NODE, NH*HD, DIM, e); }
    { EP e; e.a1 = p_gatg;                                                    // batched per-head, grid.z=NH
      e.Z = NH; e.sA = MSG; e.sB = HD; e.sC = HD; e.sAux = HD;
      gemm<8>(p_P, NH*MSG, W_gat_value, NH*HD,
              p_og, NH*HD, ROWS_NODE, HD, MSG, e); }

    // 6) node2 = node_repr + dh + og@W_gat_out
    { EP e; e.a1 = node_repr; e.a2 = p_dh;
      gemm<6>(p_og, NH*HD, W_gat_out, DIM, p_node2, DIM, ROWS_NODE, DIM, NH*HD, e); }

    // 7) node MLP + residual -> out
    ln_warp_kernel<<<ROWS_NODE/8, 256>>>(p_node2, p_nln, node_ln_g, node_ln_b, DIM);
    { EP e; e.bias = node_b1;
      gemm<2>(p_nln, DIM, node_W1, 4*DIM, p_h2, 4*DIM, ROWS_NODE, 4*DIM, DIM, e); }
    { EP e; e.bias = node_b2; e.a1 = p_node2;
      gemm<7>(p_h2, 4*DIM, node_W2, DIM, out, DIM, ROWS_NODE, DIM, 4*DIM, e); }
}

// round 10
// speedup vs baseline: 1.0401x; 1.0401x over previous
#include <cuda_runtime.h>
#include <math.h>
#include <float.h>
#include <stdint.h>

// ---------------- problem constants ----------------
#define NB   2
#define NN   1024
#define NKE  32
#define DIM  512
#define MSG  256
#define NH   16
#define HD   64
#define ROWS_MSG  (NB*NN*NKE)   // 65536
#define ROWS_NODE (NB*NN)       // 2048

// ---------------- scratch (static device globals; no runtime alloc) ----------------
__device__ float g_bufA[ROWS_MSG*MSG];
__device__ float g_bufB[ROWS_MSG*MSG];
__device__ float g_h1  [ROWS_MSG*4*MSG];
__device__ float g_node_msg[ROWS_NODE*MSG];
__device__ float g_node_tgt[ROWS_NODE*MSG];
__device__ float g_ab  [ROWS_MSG*NH];
__device__ float g_attn[ROWS_MSG*NH];
__device__ float g_P   [ROWS_NODE*NH*MSG];
__device__ float g_og  [ROWS_NODE*NH*HD];
__device__ float g_gate[ROWS_NODE*MSG];
__device__ float g_gatg[ROWS_NODE*NH*HD];
__device__ float g_o   [ROWS_NODE*MSG];
__device__ float g_dh  [ROWS_NODE*DIM];
__device__ float g_node2[ROWS_NODE*DIM];
__device__ float g_nln [ROWS_NODE*DIM];
__device__ float g_h2  [ROWS_NODE*4*DIM];

// ---------------- tf32 tensor-core GEMM, cp.async 2-stage pipeline ----------------
// Block tile 128 x BNv, BK=16, 128 threads = 4 warps in 2(m) x 2(n).
// BNv=64 : warp tile 64x32 (round-8 proven config)
// BNv=128: warp tile 64x64 (1.0 LDS/MMA, for big GEMMs with N>=256)
#define BM 128
#define BK 16
#define AS_STR 20
#define A_TILE_F (BM*AS_STR)   // 2560 floats

__device__ __forceinline__ float gelu_exact(float x) {
    return 0.5f * x * (1.0f + erff(x * 0.70710678118654752f));
}
__device__ __forceinline__ float sigmoidf_(float x) {
    return 1.0f / (1.0f + expf(-x));
}
__device__ __forceinline__ void mma8(float* c, const uint32_t* a, const uint32_t* b) {
    asm("mma.sync.aligned.m16n8k8.row.col.f32.tf32.tf32.f32 "
        "{%0,%1,%2,%3},{%4,%5,%6,%7},{%8,%9},{%0,%1,%2,%3};"
        : "+f"(c[0]), "+f"(c[1]), "+f"(c[2]), "+f"(c[3])
        : "r"(a[0]), "r"(a[1]), "r"(a[2]), "r"(a[3]), "r"(b[0]), "r"(b[1]));
}
__device__ __forceinline__ void cp16(uint32_t dst, const void* src, int bytes) {
    asm volatile("cp.async.ca.shared.global [%0], [%1], 16, %2;\n"
                 :: "r"(dst), "l"(src), "r"(bytes));
}

// MODE: 0 plain | 1 +bias | 2 gelu(+bias) | 3 leaky | 4 (+bias)*rowmask
//       5 msg0 (acc + gather(node_msg)*mask_bw + node_tgt)
//       6 aux1 + aux2 + acc | 7 aux1 + acc + bias | 8 sigmoid(aux1)*acc
// Requires: M % 128 == 0, K % 16 == 0 (true for every call site).
template<int MODE, int BNv>
__global__ __launch_bounds__(128) void gemm_tc(
    const float* __restrict__ A, int lda,
    const float* __restrict__ B, int ldb,
    float* __restrict__ C, int ldc,
    int M, int N, int K,
    const float* __restrict__ bias,
    const float* __restrict__ aux1,
    const float* __restrict__ aux2,
    const int*   __restrict__ idx,
    const float* __restrict__ auxf,
    const int*   __restrict__ rowmask,
    int sA, int sB, int sC, int sAux)
{
    constexpr int WN      = BNv / 2;          // warp N-tile (32 or 64)
    constexpr int NI      = WN / 8;           // 4 or 8
    constexpr int BS_STR  = BNv + 8;          // 72 or 136 (conflict-free)
    constexpr int B_TILE_F = BK * BS_STR;
    constexpr int B_CHUNK_IT = (BK * BNv / 4) / 128;  // 2 or 4 chunks/thread
    constexpr int BC_SH   = (BNv == 64) ? 4 : 5;      // chunks per k-row shift

    A += (size_t)blockIdx.z * sA;
    B += (size_t)blockIdx.z * sB;
    C += (size_t)blockIdx.z * sC;
    const float* aux1z = aux1 ? aux1 + (size_t)blockIdx.z * sAux : aux1;

    __shared__ __align__(16) float sm[2*A_TILE_F + 2*B_TILE_F];
    uint32_t smem_u32 = (uint32_t)__cvta_generic_to_shared(sm);

    const int tid  = threadIdx.x;
    const int lane = tid & 31;
    const int warp = tid >> 5;
    const int warpM = warp >> 1;          // 0..1 (64 rows each)
    const int warpN = warp & 1;           // 0..1 (WN cols each)
    const int g  = lane >> 2;             // 0..7
    const int t4 = lane & 3;              // 0..3
    const int row0 = blockIdx.y * BM, col0 = blockIdx.x * BNv;

    float ac[4][NI][4];
    #pragma unroll
    for (int mi = 0; mi < 4; mi++)
        #pragma unroll
        for (int ni = 0; ni < NI; ni++)
            #pragma unroll
            for (int cr = 0; cr < 4; cr++) ac[mi][ni][cr] = 0.f;

    const int T = K / BK;

    // ---- stage loader ----
    auto load_stage = [&](int kt, int s) {
        // A tile: 128 rows x 16 k = 512 16B-chunks; 4 per thread
        #pragma unroll
        for (int i = 0; i < 4; i++) {
            int c = i * 128 + tid;
            int row = c >> 2, k4 = (c & 3) << 2;
            const float* src = A + (size_t)(row0 + row) * lda + kt + k4;
            uint32_t dst = smem_u32 + ((s * A_TILE_F + row * AS_STR + k4) << 2);
            cp16(dst, src, 16);
        }
        // B tile: 16 k-rows x BNv n
        #pragma unroll
        for (int i = 0; i < B_CHUNK_IT; i++) {
            int c = i * 128 + tid;
            int kk = c >> BC_SH, n4 = (c & ((1 << BC_SH) - 1)) << 2;
            int gc = col0 + n4;
            int rem = N - gc;
            int bytes = rem >= 4 ? 16 : (rem > 0 ? rem * 4 : 0);
            const float* src = B + (size_t)(kt + kk) * ldb + (rem > 0 ? gc : 0);
            uint32_t dst = smem_u32 + ((2 * A_TILE_F + s * B_TILE_F + kk * BS_STR + n4) << 2);
            cp16(dst, src, bytes);
        }
        asm volatile("cp.async.commit_group;\n");
    };

    load_stage(0, 0);

    for (int t = 0; t < T; t++) {
        int s = t & 1;
        if (t + 1 < T) {
            load_stage((t + 1) * BK, s ^ 1);
            asm volatile("cp.async.wait_group 1;\n");
        } else {
            asm volatile("cp.async.wait_group 0;\n");
        }
        __syncthreads();

        const float* As_ = &sm[s * A_TILE_F];
        const float* Bs_ = &sm[2 * A_TILE_F + s * B_TILE_F];

        #pragma unroll
        for (int k8 = 0; k8 < BK; k8 += 8) {
            uint32_t af[4][4], bf[NI][2];
            #pragma unroll
            for (int mi = 0; mi < 4; mi++) {
                int m0 = warpM * 64 + mi * 16 + g;
                af[mi][0] = __float_as_uint(As_[(m0    ) * AS_STR + k8 + t4    ]);
                af[mi][1] = __float_as_uint(As_[(m0 + 8) * AS_STR + k8 + t4    ]);
                af[mi][2] = __float_as_uint(As_[(m0    ) * AS_STR + k8 + t4 + 4]);
                af[mi][3] = __float_as_uint(As_[(m0 + 8) * AS_STR + k8 + t4 + 4]);
            }
            #pragma unroll
            for (int ni = 0; ni < NI; ni++) {
                int n0 = warpN * WN + ni * 8 + g;
                bf[ni][0] = __float_as_uint(Bs_[(k8 + t4    ) * BS_STR + n0]);
                bf[ni][1] = __float_as_uint(Bs_[(k8 + t4 + 4) * BS_STR + n0]);
            }
            #pragma unroll
            for (int mi = 0; mi < 4; mi++)
                #pragma unroll
                for (int ni = 0; ni < NI; ni++)
                    mma8(ac[mi][ni], af[mi], bf[ni]);
        }
        __syncthreads();
    }

    // epilogue
    #pragma unroll
    for (int mi = 0; mi < 4; mi++) {
        #pragma unroll
        for (int cr = 0; cr < 4; cr++) {
            int r = row0 + warpM * 64 + mi * 16 + g + ((cr >> 1) ? 8 : 0);
            #pragma unroll
            for (int ni = 0; ni < NI; ni++) {
                int c = col0 + warpN * WN + ni * 8 + t4 * 2 + (cr & 1);
                if (c >= N) continue;
                float v = ac[mi][ni][cr];
                if (MODE == 1) {
                    v += bias[c];
                } else if (MODE == 2) {
                    v = gelu_exact(v + bias[c]);
                } else if (MODE == 3) {
                    v = (v > 0.f) ? v : 0.01f * v;
                } else if (MODE == 4) {
                    v += bias[c];
                    if (rowmask[r] == 0) v = 0.f;
                } else if (MODE == 5) {
                    int bidx = r >> 15;            // 32768 msg rows per batch
                    int node = r >> 5;             // b*NN + n
                    v += aux1z[(size_t)(bidx*NN + idx[r]) * MSG + c] * auxf[r]
                       + aux2[(size_t)node * MSG + c];
                } else if (MODE == 6) {
                    v = aux1z[(size_t)r*ldc + c] + aux2[(size_t)r*ldc + c] + v;
                } else if (MODE == 7) {
                    v = aux1z[(size_t)r*ldc + c] + v + bias[c];
                } else if (MODE == 8) {
                    v *= sigmoidf_(aux1z[(size_t)r*ldc + c]);
                }
                C[(size_t)r * ldc + c] = v;
            }
        }
    }
}

// ---------------- LayerNorm: one warp per row, float4 ----------------
__global__ __launch_bounds__(256) void ln_warp_kernel(
    const float* __restrict__ x, float* __restrict__ y,
    const float* __restrict__ g, const float* __restrict__ b, int width)
{
    int wid  = threadIdx.x >> 5;
    int lane = threadIdx.x & 31;
    int row  = blockIdx.x * 8 + wid;
    const float4* xr = reinterpret_cast<const float4*>(x + (size_t)row * width);
    int w4 = width >> 2;

    float s = 0.f, sq = 0.f;
    for (int i = lane; i < w4; i += 32) {
        float4 v = xr[i];
        s  += v.x + v.y + v.z + v.w;
        sq += v.x*v.x + v.y*v.y + v.z*v.z + v.w*v.w;
    }
    #pragma unroll
    for (int o = 16; o > 0; o >>= 1) {
        s  += __shfl_xor_sync(0xFFFFFFFFu, s,  o);
        sq += __shfl_xor_sync(0xFFFFFFFFu, sq, o);
    }
    float mean = s / width;
    float var  = sq / width - mean * mean;
    float rstd = rsqrtf(var + 1e-5f);

    const float4* g4 = reinterpret_cast<const float4*>(g);
    const float4* b4 = reinterpret_cast<const float4*>(b);
    float4* yr = reinterpret_cast<float4*>(y + (size_t)row * width);
    for (int i = lane; i < w4; i += 32) {
        float4 v = xr[i], gg = g4[i], bb = b4[i];
        float4 o;
        o.x = (v.x - mean) * rstd * gg.x + bb.x;
        o.y = (v.y - mean) * rstd * gg.y + bb.y;
        o.z = (v.z - mean) * rstd * gg.z + bb.z;
        o.w = (v.w - mean) * rstd * gg.w + bb.w;
        yr[i] = o;
    }
}

// ---------------- masked softmax over k, per (node, head) ----------------
__global__ __launch_bounds__(512) void softmax_kernel(
    const float* __restrict__ ab, const int* __restrict__ em,
    float* __restrict__ attn)
{
    int node = blockIdx.x;
    int h = threadIdx.x >> 5, k = threadIdx.x & 31;
    int ridx = node * NKE + k;
    float v = em[ridx] ? ab[(size_t)ridx * NH + h] : -FLT_MAX;
    float m = v;
    #pragma unroll
    for (int o = 16; o > 0; o >>= 1) m = fmaxf(m, __shfl_xor_sync(0xFFFFFFFFu, m, o));
    float e = expf(v - m);
    float s = e;
    #pragma unroll
    for (int o = 16; o > 0; o >>= 1) s += __shfl_xor_sync(0xFFFFFFFFu, s, o);
    attn[(size_t)ridx * NH + h] = e / s;
}

// ---------------- P[node,h,c] = sum_k attn[k,h] * msg[k,c] ----------------
__global__ __launch_bounds__(256) void pmat_kernel(
    const float* __restrict__ msg, const float* __restrict__ attn,
    float* __restrict__ P)
{
    __shared__ float ms[NKE][MSG];   // 32 KB
    __shared__ float as[NKE][NH];    // 2 KB
    int node = blockIdx.x;
    for (int e = threadIdx.x; e < NKE * MSG; e += 256)
        ms[e >> 8][e & 255] = msg[(size_t)node * NKE * MSG + e];
    for (int e = threadIdx.x; e < NKE * NH; e += 256)
        as[e >> 4][e & 15] = attn[(size_t)node * NKE * NH + e];
    __syncthreads();
    int c = threadIdx.x;   // 0..255
    #pragma unroll 1
    for (int h = 0; h < NH; h++) {
        float acc = 0.f;
        #pragma unroll
        for (int k = 0; k < NKE; k++) acc = fmaf(as[k][h], ms[k][c], acc);
        P[(size_t)node * NH * MSG + h * MSG + c] = acc;
    }
}

// ---------------- gated mean-pool over k ----------------
__global__ __launch_bounds__(256) void pool_kernel(
    const float* __restrict__ msg, const int* __restrict__ em,
    const float* __restrict__ gate_lin, float* __restrict__ o)
{
    int node = blockIdx.x;
    __shared__ float emf[NKE];
    __shared__ float cnt_s;
    if (threadIdx.x < NKE) emf[threadIdx.x] = (float)em[node * NKE + threadIdx.x];
    __syncthreads();
    if (threadIdx.x == 0) {
        float c = 0.f;
        for (int k = 0; k < NKE; k++) c += emf[k];
        cnt_s = c;
    }
    __syncthreads();
    float inv = 1.f / (cnt_s + 1e-6f);
    int c = threadIdx.x;   // 0..255
    float acc = 0.f;
    #pragma unroll
    for (int k = 0; k < NKE; k++)
        acc = fmaf(emf[k], msg[((size_t)node * NKE + k) * MSG + c], acc);
    float gl = gate_lin[(size_t)node * MSG + c];
    o[(size_t)node * MSG + c] = acc * inv * sigmoidf_(gl);
}

// ---------------- host side ----------------
struct EP {
    const float* bias = nullptr;
    const float* a1 = nullptr;
    const float* a2 = nullptr;
    const int*   idx = nullptr;
    const float* af = nullptr;
    const int*   rm = nullptr;
    int sA = 0, sB = 0, sC = 0, sAux = 0, Z = 1;
};

template<int MODE, int BNv = 64>
static void gemm(const float* A, int lda, const float* B, int ldb,
                 float* C, int ldc, int M, int N, int K, EP e = EP())
{
    dim3 g((N + BNv - 1) / BNv, (M + BM - 1) / BM, e.Z);
    gemm_tc<MODE, BNv><<<g, 128>>>(A, lda, B, ldb, C, ldc, M, N, K,
                                   e.bias, e.a1, e.a2, e.idx, e.af, e.rm,
                                   e.sA, e.sB, e.sC, e.sAux);
}

extern "C" void kernel_launch(void* const* d_in, const int* in_sizes, int n_in,
                              void* d_out, int out_size)
{
    const float* node_repr  = (const float*)d_in[0];
    const float* edge_repr  = (const float*)d_in[1];
    const int*   edge_index = (const int*)  d_in[2];
    const int*   edge_mask  = (const int*)  d_in[3];
    const float* mask_bw    = (const float*)d_in[4];
    const float* W_edge_msg = (const float*)d_in[5];
    const float* W_node_src = (const float*)d_in[6];
    const float* W_node_tgt = (const float*)d_in[7];
    const float* msg_ln_g   = (const float*)d_in[8];
    const float* msg_ln_b   = (const float*)d_in[9];
    const float* msg_W1     = (const float*)d_in[10];
    const float* msg_b1     = (const float*)d_in[11];
    const float* msg_W2     = (const float*)d_in[12];
    const float* msg_b2     = (const float*)d_in[13];
    const float* W_gate     = (const float*)d_in[14];
    const float* b_gate     = (const float*)d_in[15];
    const float* W_out      = (const float*)d_in[16];
    const float* W_msg      = (const float*)d_in[17];
    const float* W_attn_bias= (const float*)d_in[18];
    const float* W_gat_value= (const float*)d_in[19];
    const float* W_gat_gate = (const float*)d_in[20];
    const float* b_gat_gate = (const float*)d_in[21];
    const float* W_gat_out  = (const float*)d_in[22];
    const float* node_ln_g  = (const float*)d_in[23];
    const float* node_ln_b  = (const float*)d_in[24];
    const float* node_W1    = (const float*)d_in[25];
    const float* node_b1    = (const float*)d_in[26];
    const float* node_W2    = (const float*)d_in[27];
    const float* node_b2    = (const float*)d_in[28];

    float *p_bufA, *p_bufB, *p_h1, *p_node_msg, *p_node_tgt,
          *p_ab, *p_attn, *p_P, *p_og, *p_gate, *p_gatg, *p_o, *p_dh,
          *p_node2, *p_nln, *p_h2;
    cudaGetSymbolAddress((void**)&p_bufA, g_bufA);
    cudaGetSymbolAddress((void**)&p_bufB, g_bufB);
    cudaGetSymbolAddress((void**)&p_h1,  g_h1);
    cudaGetSymbolAddress((void**)&p_node_msg, g_node_msg);
    cudaGetSymbolAddress((void**)&p_node_tgt, g_node_tgt);
    cudaGetSymbolAddress((void**)&p_ab,  g_ab);
    cudaGetSymbolAddress((void**)&p_attn,g_attn);
    cudaGetSymbolAddress((void**)&p_P,   g_P);
    cudaGetSymbolAddress((void**)&p_og,  g_og);
    cudaGetSymbolAddress((void**)&p_gate,g_gate);
    cudaGetSymbolAddress((void**)&p_gatg,g_gatg);
    cudaGetSymbolAddress((void**)&p_o,   g_o);
    cudaGetSymbolAddress((void**)&p_dh,  g_dh);
    cudaGetSymbolAddress((void**)&p_node2,g_node2);
    cudaGetSymbolAddress((void**)&p_nln, g_nln);
    cudaGetSymbolAddress((void**)&p_h2,  g_h2);

    float* out = (float*)d_out;

    // buffer aliases (lifetimes disjoint)
    float* p_msg0 = p_bufA;   // until ln reads it
    float* p_msg  = p_bufA;   // final messages (overwrites msg0 after it is dead)
    float* p_ln   = p_bufB;   // until h1 GEMM reads it
    float* p_t    = p_bufB;   // leaky(msg@W_msg) (overwrites ln after it is dead)

    // 1) node projections
    gemm<0>(node_repr, DIM, W_node_src, MSG, p_node_msg, MSG, ROWS_NODE, MSG, DIM);
    gemm<0>(node_repr, DIM, W_node_tgt, MSG, p_node_tgt, MSG, ROWS_NODE, MSG, DIM);

    // 2) msg0 = edge_repr@W_edge_msg + gather(node_msg)*mask_bw + node_tgt   [big: BN=128]
    { EP e; e.a1 = p_node_msg; e.a2 = p_node_tgt; e.idx = edge_index; e.af = mask_bw;
      gemm<5,128>(edge_repr, MSG, W_edge_msg, MSG, p_msg0, MSG, ROWS_MSG, MSG, MSG, e); }

    // 3) msg MLP: LN -> gelu(W1) -> W2 (+mask-zero)   [big: BN=128]
    ln_warp_kernel<<<ROWS_MSG/8, 256>>>(p_msg0, p_ln, msg_ln_g, msg_ln_b, MSG);
    { EP e; e.bias = msg_b1;
      gemm<2,128>(p_ln, MSG, msg_W1, 4*MSG, p_h1, 4*MSG, ROWS_MSG, 4*MSG, MSG, e); }
    { EP e; e.bias = msg_b2; e.rm = edge_mask;
      gemm<4,128>(p_h1, 4*MSG, msg_W2, MSG, p_msg, MSG, ROWS_MSG, MSG, 4*MSG, e); }

    // 4) pooled gated path: gate_lin, pool, dh = o@W_out
    { EP e; e.bias = b_gate;
      gemm<1>(node_repr, DIM, W_gate, MSG, p_gate, MSG, ROWS_NODE, MSG, DIM, e); }
    pool_kernel<<<ROWS_NODE, 256>>>(p_msg, edge_mask, p_gate, p_o);
    gemm<0>(p_o, MSG, W_out, DIM, p_dh, DIM, ROWS_NODE, DIM, MSG);

    // 5) GAT path   [W_msg big: BN=128]
    gemm<3,128>(p_msg, MSG, W_msg, MSG, p_t, MSG, ROWS_MSG, MSG, MSG);        // leaky(msg@W_msg)
    gemm<0>(p_t, MSG, W_attn_bias, NH, p_ab, NH, ROWS_MSG, NH, MSG);          // ab
    softmax_kernel<<<ROWS_NODE, 512>>>(p_ab, edge_mask, p_attn);
    pmat_kernel<<<ROWS_NODE, 256>>>(p_msg, p_attn, p_P);                      // P = attn^T msg
    { EP e; e.bias = b_gat_gate;
      gemm<1>(node_repr, DIM, W_gat_gate, NH*HD, p_gatg, NH*HD, ROWS_NODE, NH*HD, DIM, e); }
    { EP e; e.a1 = p_gatg;                                                    // batched per-head, grid.z=NH
      e.Z = NH; e.sA = MSG; e.sB = HD; e.sC = HD; e.sAux = HD;
      gemm<8>(p_P, NH*MSG, W_gat_value, NH*HD,
              p_og, NH*HD, ROWS_NODE, HD, MSG, e); }

    // 6) node2 = node_repr + dh + og@W_gat_out
    { EP e; e.a1 = node_repr; e.a2 = p_dh;
      gemm<6>(p_og, NH*HD, W_gat_out, DIM, p_node2, DIM, ROWS_NODE, DIM, NH*HD, e); }

    // 7) node MLP + residual -> out   [node_W1 N=2048: BN=128]
    ln_warp_kernel<<<ROWS_NODE/8, 256>>>(p_node2, p_nln, node_ln_g, node_ln_b, DIM);
    { EP e; e.bias = node_b1;
      gemm<2,128>(p_nln, DIM, node_W1, 4*DIM, p_h2, 4*DIM, ROWS_NODE, 4*DIM, DIM, e); }
    { EP e; e.bias = node_b2; e.a1 = p_node2;
      gemm<7>(p_h2, 4*DIM, node_W2, DIM, out, DIM, ROWS_NODE, DIM, 4*DIM, e); }
}